// round 13
// baseline (speedup 1.0000x reference)
#include <cuda_runtime.h>
#include <math.h>
#include <float.h>

// ---------------------------------------------------------------------------
// PFDetLoss — R10: register-resident assign candidates (no smem buffer),
// warp-shuffle top-k; dense focal via 8KB lerp-LUT with unrolled MLP=4 loads,
// 576-CTA dense grid. 2 launches, self-cleaning state.
// ---------------------------------------------------------------------------

#define IMGF 1280.0f
#define EPSF 1e-7f
#define RADIUSF 2.5f
#define NCAND 10
#define NLOC 5                     // max candidate cells per thread (529<=640)

#define CELLS_PER_BATCH 33600      // 25600 + 6400 + 1600
#define NB 64
#define NGT 40
#define NTASK (NB * 3)
#define POSCAP (NTASK * NGT * NCAND)
#define NCHUNK 9                   // 1024-float4 chunks per batch (8400 total)
#define FGRID (NB * NCHUNK)        // 576
#define FTHREADS 256
#define LUTN 1024
#define LUT_S2 (1024.0f / 24.0f)
#define LUT_H (24.0f / 1024.0f)

// state: zero-initialized at load; self-cleaning every call.
__device__ int          g_winner[NB * CELLS_PER_BATCH];  // 0 = none, gt+1
__device__ float        g_obj   [NB * CELLS_PER_BATCH];
__device__ float        g_gt    [NTASK * NGT * 6];       // cxg, cyg, tw, th, fx, fy
__device__ float        g_acc   [NTASK * 4];             // focal, box, foot, pm
__device__ int          g_pos   [POSCAP];                // (task<<16)|cell
__device__ int          g_pos_cnt;
__device__ unsigned int g_done;
__device__ float4       g_lut2  [LUTN / 2];              // float2: (f, df)

__device__ __forceinline__ float sigf(float x) { return 1.0f / (1.0f + expf(-x)); }
__device__ __forceinline__ float clamp5(float x) { return fminf(fmaxf(x, -5.0f), 5.0f); }

__device__ __forceinline__ void level_params(int level, int& W, int& HW, float& s, int& off) {
    if (level == 0)      { W = 160; HW = 25600; s = 8.0f  / IMGF; off = 0; }
    else if (level == 1) { W = 80;  HW = 6400;  s = 16.0f / IMGF; off = 25600; }
    else                 { W = 40;  HW = 1600;  s = 32.0f / IMGF; off = 32000; }
}

__device__ __forceinline__ float focal0_exact(float x) {
    float t = expf(-fabsf(x));
    float r = 1.0f / (1.0f + t);
    float prob = (x >= 0.0f) ? r : t * r;
    float ce0 = fmaxf(x, 0.0f) + log1pf(t);
    return 0.75f * prob * prob * ce0;
}

__device__ __forceinline__ int nearest_cell(float c, int n) {
    int lo = (int)floorf(c);
    int g0 = min(max(lo, 0), n - 1);
    int g1 = min(max(lo + 1, 0), n - 1);
    float f0 = ((float)g0 - c) * ((float)g0 - c);
    float f1 = ((float)g1 - c) * ((float)g1 - c);
    return (f1 < f0) ? g1 : g0;
}

__device__ __forceinline__ void cell_iou_cost(
    const float* __restrict__ base, int HW, int i, float gx, float gy, float s,
    float gX1, float gY1, float gX2, float gY2, float gArea,
    float& iou, float& cost)
{
    float o  = base[i];
    float x1 = base[HW + i],     x2 = base[2 * HW + i];
    float x3 = base[3 * HW + i], x4 = base[4 * HW + i];
    float pcx = (sigf(x1) + gx) * s;
    float pcy = (sigf(x2) + gy) * s;
    float pw = expf(clamp5(x3)) * s;
    float ph = expf(clamp5(x4)) * s;
    float pX1 = pcx - pw * 0.5f, pY1 = pcy - ph * 0.5f;
    float pX2 = pcx + pw * 0.5f, pY2 = pcy + ph * 0.5f;

    float ltx = fmaxf(pX1, gX1), lty = fmaxf(pY1, gY1);
    float rbx = fminf(pX2, gX2), rby = fminf(pY2, gY2);
    float iw = fmaxf(rbx - ltx, 0.0f), ih = fmaxf(rby - lty, 0.0f);
    float inter = iw * ih;
    float pArea = (pX2 - pX1) * (pY2 - pY1);
    iou = inter / (pArea + gArea - inter + EPSF);

    float clsc = fmaxf(-o, 0.0f) + log1pf(expf(-fabsf(o)));
    cost = clsc - 3.0f * logf(iou + EPSF);
}

__device__ __forceinline__ void claim_cell(int task, int cbase, int c, int gt, float bestiou) {
    int old = atomicMax(&g_winner[cbase + c], gt + 1);
    if (old == 0) {
        int slot = atomicAdd(&g_pos_cnt, 1);
        g_pos[slot] = (task << 16) | c;
    }
    atomicMax((int*)&g_obj[cbase + c], __float_as_int(bestiou));
}

// ---------------------------------------------------------------------------
// One CTA per (task, gt). 128 threads. Candidates in registers (<=5/thread).
__global__ __launch_bounds__(128) void assign_kernel(
    const float* __restrict__ p0, const float* __restrict__ p1,
    const float* __restrict__ p2, const float* __restrict__ tgt)
{
    const int bid = blockIdx.x;
    const int tid = threadIdx.x;
    const int wid = tid >> 5;
    const int lane = tid & 31;

    if (bid < 8) {   // lerp-LUT build: 8 CTAs x 128 = 1024 entries
        int e = bid * 128 + tid;
        float x0 = ((float)(e - 512)) * LUT_H;
        float f0 = focal0_exact(x0);
        float f1 = focal0_exact(x0 + LUT_H);
        ((float2*)g_lut2)[e] = make_float2(f0, f1 - f0);
    }

    const int gt   = bid % NGT;
    const int task = bid / NGT;
    const int level = task % 3;
    const int b     = task / 3;

    const float* t = tgt + ((size_t)b * NGT + gt) * 7;
    const float cls = t[0];
    const float cx = t[1], cy = t[2], w = t[3], h = t[4];
    const float fx = t[5], fy = t[6];

    const float size = fmaxf(w, h) * IMGF;
    bool sm;
    if (level == 0)      sm = (size < 128.0f);
    else if (level == 1) sm = (size >= 48.0f) && (size < 288.0f);
    else                 sm = (size >= 128.0f);
    if (!(cls == 0.0f && sm)) return;   // invalid GT: exact no-op

    int W, HW, off; float s;
    level_params(level, W, HW, s, off);
    const float* pr = (level == 0) ? p0 : (level == 1) ? p1 : p2;
    const float* base = pr + (size_t)b * 7 * HW;
    const int cbase = b * CELLS_PER_BATCH + off;

    const float cxg = cx / s, cyg = cy / s;
    const float bx1 = (cx - w * 0.5f) / s, bx2 = (cx + w * 0.5f) / s;
    const float by1 = (cy - h * 0.5f) / s, by2 = (cy + h * 0.5f) / s;

    const float gX1 = cx - w * 0.5f, gY1 = cy - h * 0.5f;
    const float gX2 = cx + w * 0.5f, gY2 = cy + h * 0.5f;
    const float gArea = (gX2 - gX1) * (gY2 - gY1);

    int gx_lo = max(0,     (int)floorf(fminf(cxg - RADIUSF, bx1)) - 1);
    int gx_hi = min(W - 1, (int)ceilf (fmaxf(cxg + RADIUSF, bx2)) + 1);
    int gy_lo = max(0,     (int)floorf(fminf(cyg - RADIUSF, by1)) - 1);
    int gy_hi = min(W - 1, (int)ceilf (fmaxf(cyg + RADIUSF, by2)) + 1);
    int rw = gx_hi - gx_lo + 1;
    int rh = gy_hi - gy_lo + 1;
    int ncells = (rw > 0 && rh > 0) ? rw * rh : 0;   // <= 529 always

    // ---- gather candidates into registers ----
    float c_cost[NLOC], c_iou[NLOC];
    int   c_idx [NLOC];
#pragma unroll
    for (int k = 0; k < NLOC; k++) { c_cost[k] = FLT_MAX; c_idx[k] = 0x7fffffff; c_iou[k] = 0.0f; }
    float iousum_l = 0.0f;
    int   ncand_l = 0;

#pragma unroll
    for (int k = 0; k < NLOC; k++) {
        int kk = tid + k * 128;
        if (kk < ncells) {
            int gxi = gx_lo + kk % rw;
            int gyi = gy_lo + kk / rw;
            float gx = (float)gxi, gy = (float)gyi;
            bool inc = (fabsf(gx - cxg) < RADIUSF) && (fabsf(gy - cyg) < RADIUSF);
            bool inb = (gx >= bx1) && (gx < bx2) && (gy >= by1) && (gy < by2);
            if (inc || inb) {
                int i = gyi * W + gxi;
                float iou, cost;
                cell_iou_cost(base, HW, i, gx, gy, s, gX1, gY1, gX2, gY2, gArea, iou, cost);
                c_cost[k] = cost; c_idx[k] = i; c_iou[k] = iou;
                iousum_l += iou;
                ncand_l++;
            }
        }
    }

    __shared__ float swf[4];
    __shared__ int   swi[4];
    __shared__ float s_minc[4];
    __shared__ int   s_mini[4];
    __shared__ int   s_sel[NCAND];
    __shared__ float s_bestiou;
    __shared__ int   s_npos;
    __shared__ int   s_ncand;

    // iou_sum + n_cand: warp shfl + cross-warp
#pragma unroll
    for (int o = 16; o > 0; o >>= 1) {
        iousum_l += __shfl_down_sync(0xffffffffu, iousum_l, o);
        ncand_l  += __shfl_down_sync(0xffffffffu, ncand_l, o);
    }
    if (lane == 0) { swf[wid] = iousum_l; swi[wid] = ncand_l; }
    __syncthreads();
    if (tid == 0) {
        float isum = (swf[0] + swf[1]) + (swf[2] + swf[3]);
        int nc = swi[0] + swi[1] + swi[2] + swi[3];
        s_ncand = nc;
        int np = (int)floorf(isum);
        int hi = (NCAND < nc) ? NCAND : nc;
        if (np < 1) np = 1;
        if (np > hi) np = hi;
        s_npos = np;
    }
    __syncthreads();
    const int n_cand = s_ncand;

    if (n_cand == 0) {
        if (tid == 0) {
            int gxi = nearest_cell(cxg, W);
            int gyi = nearest_cell(cyg, W);
            int i = gyi * W + gxi;
            float iou, cost;
            cell_iou_cost(base, HW, i, (float)gxi, (float)gyi, s,
                          gX1, gY1, gX2, gY2, gArea, iou, cost);
            claim_cell(task, cbase, i, gt, iou);
            float* gp = &g_gt[((size_t)task * NGT + gt) * 6];
            gp[0] = cxg; gp[1] = cyg;
            gp[2] = expf(logf(w / s + EPSF)) * s;
            gp[3] = expf(logf(h / s + EPSF)) * s;
            gp[4] = fx; gp[5] = fy;
        }
        return;
    }

    const int n_pos = s_npos;

    // ---- n_pos selection rounds: reg-local min -> warp shfl -> 4-way smem ----
    for (int r = 0; r < n_pos; r++) {
        float mc = FLT_MAX; int mi = 0x7fffffff;
#pragma unroll
        for (int k = 0; k < NLOC; k++) {
            if (c_cost[k] < mc || (c_cost[k] == mc && c_idx[k] < mi)) { mc = c_cost[k]; mi = c_idx[k]; }
        }
#pragma unroll
        for (int o = 16; o > 0; o >>= 1) {
            float oc = __shfl_down_sync(0xffffffffu, mc, o);
            int   oi = __shfl_down_sync(0xffffffffu, mi, o);
            if (oc < mc || (oc == mc && oi < mi)) { mc = oc; mi = oi; }
        }
        if (lane == 0) { s_minc[wid] = mc; s_mini[wid] = mi; }
        __syncthreads();
        if (tid == 0) {
            float bc = s_minc[0]; int bi = s_mini[0];
#pragma unroll
            for (int q = 1; q < 4; q++) {
                if (s_minc[q] < bc || (s_minc[q] == bc && s_mini[q] < bi)) { bc = s_minc[q]; bi = s_mini[q]; }
            }
            s_sel[r] = bi;
            s_mini[0] = bi;    // broadcast winner idx
        }
        __syncthreads();
        int widx = s_mini[0];
        // owner (unique cell idx) invalidates its entry; round 0 records best iou
#pragma unroll
        for (int k = 0; k < NLOC; k++) {
            if (c_idx[k] == widx) {
                if (r == 0) s_bestiou = c_iou[k];
                c_cost[k] = FLT_MAX; c_idx[k] = 0x7fffffff;
            }
        }
    }
    __syncthreads();   // s_bestiou + invalidations visible

    if (tid < n_pos) {
        claim_cell(task, cbase, s_sel[tid], gt, s_bestiou);
    }
    if (tid == 0) {
        float* gp = &g_gt[((size_t)task * NGT + gt) * 6];
        gp[0] = cxg; gp[1] = cyg;
        gp[2] = expf(logf(w / s + EPSF)) * s;
        gp[3] = expf(logf(h / s + EPSF)) * s;
        gp[4] = fx; gp[5] = fy;
    }
}

// ---------------------------------------------------------------------------
// Fused: dense lerp-LUT focal (576 CTAs, 4 unrolled float4 loads/thread) +
// sparse positives + final reduction + cleanup.
__global__ __launch_bounds__(FTHREADS) void fused_kernel(
    const float* __restrict__ p0, const float* __restrict__ p1,
    const float* __restrict__ p2, float* __restrict__ out)
{
    __shared__ float2 slut2[LUTN];          // 8KB
    __shared__ float sred[3][8];
    __shared__ float sfin[FTHREADS];
    const int tid = threadIdx.x;
    const int bid = blockIdx.x;
    const int wid = tid >> 5;
    const int lane = tid & 31;

    // fill LUT: 512 float4 / 256 threads = 2 loads
    {
        float4* d = (float4*)slut2;
#pragma unroll
        for (int k = 0; k < 2; k++) d[tid + k * FTHREADS] = g_lut2[tid + k * FTHREADS];
    }
    __syncthreads();

    const int b = bid / NCHUNK;
    const int c = bid % NCHUNK;
    const int cbase = c * 1024;
    const int cend  = min(cbase + 1024, 8400);
    const float4* c00 = (const float4*)(p0 + (size_t)b * 7 * 25600);
    const float4* c01 = (const float4*)(p1 + (size_t)b * 7 * 6400);
    const float4* c02 = (const float4*)(p2 + (size_t)b * 7 * 1600);

    // issue all loads up-front (MLP=4)
    float4 v[4]; int lv[4]; bool ok[4];
#pragma unroll
    for (int k = 0; k < 4; k++) {
        int j = cbase + tid + k * FTHREADS;
        ok[k] = (j < cend);
        if (ok[k]) {
            const float4* ptr;
            if (j < 6400)      { ptr = c00 + j;        lv[k] = 0; }
            else if (j < 8000) { ptr = c01 + (j - 6400); lv[k] = 1; }
            else               { ptr = c02 + (j - 8000); lv[k] = 2; }
            v[k] = *ptr;
        }
    }

    float a0 = 0.0f, a1 = 0.0f, a2 = 0.0f;
#pragma unroll
    for (int k = 0; k < 4; k++) {
        if (ok[k]) {
            float fs = 0.0f;
            float xs[4] = {v[k].x, v[k].y, v[k].z, v[k].w};
#pragma unroll
            for (int q = 0; q < 4; q++) {
                float tt = fmaf(xs[q], LUT_S2, 512.0f);
                tt = fminf(fmaxf(tt, 0.0f), 1023.0f);
                float fi = floorf(tt);
                int ii = (int)fi;
                float fr = tt - fi;
                float2 e = slut2[ii];
                fs += fmaf(fr, e.y, e.x);
            }
            if (lv[k] == 0) a0 += fs; else if (lv[k] == 1) a1 += fs; else a2 += fs;
        }
    }
    // warp reduce 3 accs
#pragma unroll
    for (int o = 16; o > 0; o >>= 1) {
        a0 += __shfl_down_sync(0xffffffffu, a0, o);
        a1 += __shfl_down_sync(0xffffffffu, a1, o);
        a2 += __shfl_down_sync(0xffffffffu, a2, o);
    }
    if (lane == 0) { sred[0][wid] = a0; sred[1][wid] = a1; sred[2][wid] = a2; }
    __syncthreads();
    if (tid < 3) {
        float sum = 0.0f;
#pragma unroll
        for (int q = 0; q < 8; q++) sum += sred[tid][q];
        if (sum != 0.0f) atomicAdd(&g_acc[(b * 3 + tid) * 4 + 0], sum);
    }

    // ---- sparse positive cells ----
    const int cnt = min(g_pos_cnt, POSCAP);
    for (int k = bid * FTHREADS + tid; k < cnt; k += FGRID * FTHREADS) {
        int e = g_pos[k];
        int etask = e >> 16;
        int i = e & 0xFFFF;
        int elevel = etask % 3, eb = etask / 3;
        int eW, eHW, eoff; float es;
        level_params(elevel, eW, eHW, es, eoff);
        const float* epr = (elevel == 0) ? p0 : (elevel == 1) ? p1 : p2;
        const float* base = epr + (size_t)eb * 7 * eHW;
        int widxg = eb * CELLS_PER_BATCH + eoff + i;

        int wv = g_winner[widxg];
        float z = g_obj[widxg];
        g_winner[widxg] = 0;          // self-clean
        g_obj[widxg] = 0.0f;
        int gt = wv - 1;
        const float* gp = &g_gt[((size_t)etask * NGT + gt) * 6];

        float x = base[i];
        {
            float t = expf(-fabsf(x));
            float lg = log1pf(t);
            float prob = sigf(x);
            float ce = fmaxf(x, 0.0f) - x * z + lg;
            float pt = prob * z + (1.0f - prob) * (1.0f - z);
            float at = 0.25f * z + 0.75f * (1.0f - z);
            float om = 1.0f - pt;
            float fz = at * om * om * ce;
            float f0 = 0.75f * prob * prob * (fmaxf(x, 0.0f) + lg);
            atomicAdd(&g_acc[etask * 4 + 0], fz - f0);
        }
        float gx = (float)(i % eW), gy = (float)(i / eW);
        float tcx = gp[0] * es, tcy = gp[1] * es;
        float tw = gp[2], th = gp[3];

        float x1 = base[eHW + i],     x2 = base[2 * eHW + i];
        float x3 = base[3 * eHW + i], x4 = base[4 * eHW + i];
        float pcx = (sigf(x1) + gx) * es;
        float pcy = (sigf(x2) + gy) * es;
        float pw = expf(clamp5(x3)) * es;
        float ph = expf(clamp5(x4)) * es;

        float pX1 = pcx - pw * 0.5f, pY1 = pcy - ph * 0.5f;
        float pX2 = pcx + pw * 0.5f, pY2 = pcy + ph * 0.5f;
        float tX1 = tcx - tw * 0.5f, tY1 = tcy - th * 0.5f;
        float tX2 = tcx + tw * 0.5f, tY2 = tcy + th * 0.5f;

        float iw = fmaxf(fminf(pX2, tX2) - fmaxf(pX1, tX1), 0.0f);
        float ih = fmaxf(fminf(pY2, tY2) - fmaxf(pY1, tY1), 0.0f);
        float inter = iw * ih;
        float uni = pw * ph + tw * th - inter + EPSF;
        float iou = inter / uni;
        float rho2 = (pcx - tcx) * (pcx - tcx) + (pcy - tcy) * (pcy - tcy);
        float cw = fmaxf(pX2, tX2) - fminf(pX1, tX1);
        float ch = fmaxf(pY2, tY2) - fminf(pY1, tY1);
        float c2 = cw * cw + ch * ch + EPSF;
        const float PI = 3.14159265358979323846f;
        float dat = atanf(tw / (th + EPSF)) - atanf(pw / (ph + EPSF));
        float vv = (4.0f / (PI * PI)) * dat * dat;
        float alpha = vv / (1.0f - iou + vv + EPSF);
        float ciou = iou - rho2 / c2 - alpha * vv;
        atomicAdd(&g_acc[etask * 4 + 1], 1.0f - ciou);

        float p5 = base[5 * eHW + i], p6 = base[6 * eHW + i];
        float f0 = sigf(p5), f1 = sigf(p6);
        float d0 = fabsf(f0 - gp[4]), d1 = fabsf(f1 - gp[5]);
        float sl = (d0 < 1.0f ? 0.5f * d0 * d0 : d0 - 0.5f)
                 + (d1 < 1.0f ? 0.5f * d1 * d1 : d1 - 0.5f);
        atomicAdd(&g_acc[etask * 4 + 2], sl);
        atomicAdd(&g_acc[etask * 4 + 3], 1.0f);
    }

    // ---- last CTA: final reduction + state reset ----
    __threadfence();
    __shared__ int slast;
    if (tid == 0) slast = (atomicAdd(&g_done, 1u) == FGRID - 1) ? 1 : 0;
    __syncthreads();
    if (!slast) return;

    float vfin = 0.0f;
    if (tid < NTASK) {
        int lvv = tid % 3;
        float HWf = (lvv == 0) ? 25600.0f : (lvv == 1) ? 6400.0f : 1600.0f;
        float f  = g_acc[tid * 4 + 0];
        float bx = g_acc[tid * 4 + 1];
        float ft = g_acc[tid * 4 + 2];
        float pm = g_acc[tid * 4 + 3];
        float npos = fmaxf(pm, 1.0f);
        vfin = (f / HWf) + 5.0f * (bx / npos) + (ft / npos);
    }
    sfin[tid] = vfin;
    __syncthreads();
    for (int j = tid; j < NTASK * 4; j += FTHREADS) g_acc[j] = 0.0f;
    if (tid == 0) { g_pos_cnt = 0; g_done = 0u; }
    for (int st = FTHREADS / 2; st > 0; st >>= 1) {
        if (tid < st) sfin[tid] += sfin[tid + st];
        __syncthreads();
    }
    if (tid == 0) out[0] = sfin[0] / (float)NB;
}

// ---------------------------------------------------------------------------
extern "C" void kernel_launch(void* const* d_in, const int* in_sizes, int n_in,
                              void* d_out, int out_size)
{
    const float* p0  = (const float*)d_in[0];
    const float* p1  = (const float*)d_in[1];
    const float* p2  = (const float*)d_in[2];
    const float* tgt = (const float*)d_in[3];
    float* out = (float*)d_out;

    assign_kernel<<<NTASK * NGT, 128>>>(p0, p1, p2, tgt);
    fused_kernel<<<FGRID, FTHREADS>>>(p0, p1, p2, out);
}

// round 15
// speedup vs baseline: 1.4940x; 1.4940x over previous
#include <cuda_runtime.h>
#include <math.h>
#include <float.h>

// ---------------------------------------------------------------------------
// PFDetLoss — R14 (resubmit; prior run died to infra): R9 fused inner loop
// (nearest 16KB LUT) at grid 512; R9 assign gather + warp0-only top-k
// selection (no block barriers in rounds). 2 launches, self-cleaning state.
// ---------------------------------------------------------------------------

#define IMGF 1280.0f
#define EPSF 1e-7f
#define RADIUSF 2.5f
#define NCAND 10
#define CAP 1024

#define CELLS_PER_BATCH 33600      // 25600 + 6400 + 1600
#define NB 64
#define NGT 40
#define NTASK (NB * 3)
#define POSCAP (NTASK * NGT * NCAND)
#define FGRID 512                  // 64 batches x 8 eighths
#define FTHREADS 256
#define QF4 1050                   // float4 per eighth (8400 per batch)
#define LUTN 4096
#define LUT_S (4096.0f / 24.0f)
#define LUT_STEP (24.0f / 4096.0f)

// state: zero-initialized at load; self-cleaning every call.
__device__ int          g_winner[NB * CELLS_PER_BATCH];  // 0 = none, gt+1
__device__ float        g_obj   [NB * CELLS_PER_BATCH];
__device__ float        g_gt    [NTASK * NGT * 6];       // cxg, cyg, tw, th, fx, fy
__device__ float        g_acc   [NTASK * 4];             // focal, box, foot, pm
__device__ int          g_pos   [POSCAP];                // (task<<16)|cell
__device__ int          g_pos_cnt;
__device__ unsigned int g_done;
__device__ float4       g_lut   [LUTN / 4];

__device__ __forceinline__ float sigf(float x) { return 1.0f / (1.0f + expf(-x)); }
__device__ __forceinline__ float clamp5(float x) { return fminf(fmaxf(x, -5.0f), 5.0f); }

__device__ __forceinline__ void level_params(int level, int& W, int& HW, float& s, int& off) {
    if (level == 0)      { W = 160; HW = 25600; s = 8.0f  / IMGF; off = 0; }
    else if (level == 1) { W = 80;  HW = 6400;  s = 16.0f / IMGF; off = 25600; }
    else                 { W = 40;  HW = 1600;  s = 32.0f / IMGF; off = 32000; }
}

__device__ __forceinline__ float focal0_exact(float x) {
    float t = expf(-fabsf(x));
    float r = 1.0f / (1.0f + t);
    float prob = (x >= 0.0f) ? r : t * r;
    float ce0 = fmaxf(x, 0.0f) + log1pf(t);
    return 0.75f * prob * prob * ce0;
}

__device__ __forceinline__ int nearest_cell(float c, int n) {
    int lo = (int)floorf(c);
    int g0 = min(max(lo, 0), n - 1);
    int g1 = min(max(lo + 1, 0), n - 1);
    float f0 = ((float)g0 - c) * ((float)g0 - c);
    float f1 = ((float)g1 - c) * ((float)g1 - c);
    return (f1 < f0) ? g1 : g0;
}

__device__ __forceinline__ void cell_iou_cost(
    const float* __restrict__ base, int HW, int i, float gx, float gy, float s,
    float gX1, float gY1, float gX2, float gY2, float gArea,
    float& iou, float& cost)
{
    float o  = base[i];
    float x1 = base[HW + i],     x2 = base[2 * HW + i];
    float x3 = base[3 * HW + i], x4 = base[4 * HW + i];
    float pcx = (sigf(x1) + gx) * s;
    float pcy = (sigf(x2) + gy) * s;
    float pw = expf(clamp5(x3)) * s;
    float ph = expf(clamp5(x4)) * s;
    float pX1 = pcx - pw * 0.5f, pY1 = pcy - ph * 0.5f;
    float pX2 = pcx + pw * 0.5f, pY2 = pcy + ph * 0.5f;

    float ltx = fmaxf(pX1, gX1), lty = fmaxf(pY1, gY1);
    float rbx = fminf(pX2, gX2), rby = fminf(pY2, gY2);
    float iw = fmaxf(rbx - ltx, 0.0f), ih = fmaxf(rby - lty, 0.0f);
    float inter = iw * ih;
    float pArea = (pX2 - pX1) * (pY2 - pY1);
    iou = inter / (pArea + gArea - inter + EPSF);

    float clsc = fmaxf(-o, 0.0f) + log1pf(expf(-fabsf(o)));
    cost = clsc - 3.0f * logf(iou + EPSF);
}

__device__ __forceinline__ void claim_cell(int task, int cbase, int c, int gt, float bestiou) {
    int old = atomicMax(&g_winner[cbase + c], gt + 1);
    if (old == 0) {
        int slot = atomicAdd(&g_pos_cnt, 1);
        g_pos[slot] = (task << 16) | c;
    }
    atomicMax((int*)&g_obj[cbase + c], __float_as_int(bestiou));
}

// ---------------------------------------------------------------------------
// One CTA per (task, gt). 128 threads. bid < 32 also builds the focal LUT.
__global__ __launch_bounds__(128) void assign_kernel(
    const float* __restrict__ p0, const float* __restrict__ p1,
    const float* __restrict__ p2, const float* __restrict__ tgt)
{
    const int bid = blockIdx.x;
    const int tid = threadIdx.x;
    const int wid = tid >> 5;
    const int lane = tid & 31;

    if (bid < 32) {   // LUT build: 32 CTAs x 128 threads = 4096 entries
        int e = bid * 128 + tid;
        float x = ((float)(e - 2048)) * LUT_STEP;
        ((float*)g_lut)[e] = focal0_exact(x);
    }

    const int gt   = bid % NGT;
    const int task = bid / NGT;
    const int level = task % 3;
    const int b     = task / 3;

    const float* t = tgt + ((size_t)b * NGT + gt) * 7;
    const float cls = t[0];
    const float cx = t[1], cy = t[2], w = t[3], h = t[4];
    const float fx = t[5], fy = t[6];

    const float size = fmaxf(w, h) * IMGF;
    bool sm;
    if (level == 0)      sm = (size < 128.0f);
    else if (level == 1) sm = (size >= 48.0f) && (size < 288.0f);
    else                 sm = (size >= 128.0f);
    if (!(cls == 0.0f && sm)) return;   // invalid GT: exact no-op

    int W, HW, off; float s;
    level_params(level, W, HW, s, off);
    const float* pr = (level == 0) ? p0 : (level == 1) ? p1 : p2;
    const float* base = pr + (size_t)b * 7 * HW;
    const int cbase = b * CELLS_PER_BATCH + off;

    const float cxg = cx / s, cyg = cy / s;
    const float bx1 = (cx - w * 0.5f) / s, bx2 = (cx + w * 0.5f) / s;
    const float by1 = (cy - h * 0.5f) / s, by2 = (cy + h * 0.5f) / s;

    const float gX1 = cx - w * 0.5f, gY1 = cy - h * 0.5f;
    const float gX2 = cx + w * 0.5f, gY2 = cy + h * 0.5f;
    const float gArea = (gX2 - gX1) * (gY2 - gY1);

    int gx_lo = max(0,     (int)floorf(fminf(cxg - RADIUSF, bx1)) - 1);
    int gx_hi = min(W - 1, (int)ceilf (fmaxf(cxg + RADIUSF, bx2)) + 1);
    int gy_lo = max(0,     (int)floorf(fminf(cyg - RADIUSF, by1)) - 1);
    int gy_hi = min(W - 1, (int)ceilf (fmaxf(cyg + RADIUSF, by2)) + 1);
    int rw = gx_hi - gx_lo + 1;
    int rh = gy_hi - gy_lo + 1;
    int ncells = (rw > 0 && rh > 0) ? rw * rh : 0;

    __shared__ int   s_cnt;
    __shared__ float s_cost[CAP];
    __shared__ int   s_idx [CAP];
    __shared__ float s_iou [CAP];
    __shared__ float rf[128];
    __shared__ int   s_sel[NCAND];
    __shared__ float s_bestiou;
    __shared__ int   s_npos;

    if (tid == 0) s_cnt = 0;
    __syncthreads();

    float iousum_l = 0.0f;
    for (int k = tid; k < ncells; k += 128) {
        int gxi = gx_lo + k % rw;
        int gyi = gy_lo + k / rw;
        float gx = (float)gxi, gy = (float)gyi;
        bool inc = (fabsf(gx - cxg) < RADIUSF) && (fabsf(gy - cyg) < RADIUSF);
        bool inb = (gx >= bx1) && (gx < bx2) && (gy >= by1) && (gy < by2);
        if (!(inc || inb)) continue;
        int i = gyi * W + gxi;
        float iou, cost;
        cell_iou_cost(base, HW, i, gx, gy, s, gX1, gY1, gX2, gY2, gArea, iou, cost);
        iousum_l += iou;
        int slot = atomicAdd(&s_cnt, 1);
        if (slot < CAP) { s_cost[slot] = cost; s_idx[slot] = i; s_iou[slot] = iou; }
    }

    // deterministic iou_sum reduction (fixed tree)
    rf[tid] = iousum_l;
    __syncthreads();
    for (int st = 64; st > 0; st >>= 1) {
        if (tid < st) rf[tid] += rf[tid + st];
        __syncthreads();
    }
    const float iou_sum = rf[0];
    const int n_cand = min(s_cnt, CAP);
    __syncthreads();

    if (n_cand == 0) {
        if (tid == 0) {
            int gxi = nearest_cell(cxg, W);
            int gyi = nearest_cell(cyg, W);
            int i = gyi * W + gxi;
            float iou, cost;
            cell_iou_cost(base, HW, i, (float)gxi, (float)gyi, s,
                          gX1, gY1, gX2, gY2, gArea, iou, cost);
            claim_cell(task, cbase, i, gt, iou);
            float* gp = &g_gt[((size_t)task * NGT + gt) * 6];
            gp[0] = cxg; gp[1] = cyg;
            gp[2] = expf(logf(w / s + EPSF)) * s;
            gp[3] = expf(logf(h / s + EPSF)) * s;
            gp[4] = fx; gp[5] = fy;
        }
        return;
    }

    // ---- warp 0 does all selection rounds (no block barriers inside) ----
    if (wid == 0) {
        int np = (int)floorf(iou_sum);
        int hi = (NCAND < n_cand) ? NCAND : n_cand;
        if (np < 1) np = 1;
        if (np > hi) np = hi;
        if (lane == 0) s_npos = np;

        for (int r = 0; r < np; r++) {
            float mv = FLT_MAX; int mi = 0x7fffffff; int ms = -1;
            for (int k = lane; k < n_cand; k += 32) {
                float v = s_cost[k]; int ii = s_idx[k];
                if (v < mv || (v == mv && ii < mi)) { mv = v; mi = ii; ms = k; }
            }
#pragma unroll
            for (int o = 16; o > 0; o >>= 1) {
                float ov = __shfl_down_sync(0xffffffffu, mv, o);
                int   oi = __shfl_down_sync(0xffffffffu, mi, o);
                int   os = __shfl_down_sync(0xffffffffu, ms, o);
                if (ov < mv || (ov == mv && oi < mi)) { mv = ov; mi = oi; ms = os; }
            }
            if (lane == 0) {
                s_sel[r] = mi;
                if (r == 0) s_bestiou = s_iou[ms];
                s_cost[ms] = FLT_MAX;
            }
            __syncwarp();
        }
    }
    __syncthreads();

    const int n_pos = s_npos;
    if (tid < n_pos) {
        claim_cell(task, cbase, s_sel[tid], gt, s_bestiou);
    }
    if (tid == 0) {
        float* gp = &g_gt[((size_t)task * NGT + gt) * 6];
        gp[0] = cxg; gp[1] = cyg;
        gp[2] = expf(logf(w / s + EPSF)) * s;
        gp[3] = expf(logf(h / s + EPSF)) * s;
        gp[4] = fx; gp[5] = fy;
    }
}

// ---------------------------------------------------------------------------
// Fused: dense LUT focal (one CTA = one eighth of one batch's concatenated
// channel-0 stream) + sparse positives + final reduction + cleanup.
__global__ __launch_bounds__(FTHREADS) void fused_kernel(
    const float* __restrict__ p0, const float* __restrict__ p1,
    const float* __restrict__ p2, float* __restrict__ out)
{
    __shared__ float4 slut4[LUTN / 4];      // 16KB
    const float* slut = (const float*)slut4;
    __shared__ float sred[3][8];
    __shared__ float sfin[FTHREADS];
    const int tid = threadIdx.x;
    const int bid = blockIdx.x;
    const int wid = tid >> 5;
    const int lane = tid & 31;

    // fill LUT: 1024 float4 / 256 threads = 4 loads (L2-resident)
#pragma unroll
    for (int k = 0; k < 4; k++) slut4[tid + k * FTHREADS] = g_lut[tid + k * FTHREADS];
    __syncthreads();

    const int b = bid >> 3;        // batch
    const int q = bid & 7;         // eighth
    const float4* c00 = (const float4*)(p0 + (size_t)b * 7 * 25600);
    const float4* c01 = (const float4*)(p1 + (size_t)b * 7 * 6400);
    const float4* c02 = (const float4*)(p2 + (size_t)b * 7 * 1600);

    float a0 = 0.0f, a1 = 0.0f, a2 = 0.0f;
    const int jlo = q * QF4, jhi = jlo + QF4;
    for (int j = jlo + tid; j < jhi; j += FTHREADS) {
        float4 v;
        int lv;
        if (j < 6400)      { v = c00[j];        lv = 0; }
        else if (j < 8000) { v = c01[j - 6400]; lv = 1; }
        else               { v = c02[j - 8000]; lv = 2; }
        int i0 = __float2int_rn(fmaf(v.x, LUT_S, 2048.0f));
        int i1 = __float2int_rn(fmaf(v.y, LUT_S, 2048.0f));
        int i2 = __float2int_rn(fmaf(v.z, LUT_S, 2048.0f));
        int i3 = __float2int_rn(fmaf(v.w, LUT_S, 2048.0f));
        i0 = max(0, min(LUTN - 1, i0));
        i1 = max(0, min(LUTN - 1, i1));
        i2 = max(0, min(LUTN - 1, i2));
        i3 = max(0, min(LUTN - 1, i3));
        float fsum = (slut[i0] + slut[i1]) + (slut[i2] + slut[i3]);
        if (lv == 0) a0 += fsum; else if (lv == 1) a1 += fsum; else a2 += fsum;
    }
    // warp reduce 3 accs, then 8-warp combine
#pragma unroll
    for (int o = 16; o > 0; o >>= 1) {
        a0 += __shfl_down_sync(0xffffffffu, a0, o);
        a1 += __shfl_down_sync(0xffffffffu, a1, o);
        a2 += __shfl_down_sync(0xffffffffu, a2, o);
    }
    if (lane == 0) { sred[0][wid] = a0; sred[1][wid] = a1; sred[2][wid] = a2; }
    __syncthreads();
    if (tid < 3) {
        float sum = 0.0f;
#pragma unroll
        for (int qq = 0; qq < 8; qq++) sum += sred[tid][qq];
        if (sum != 0.0f) atomicAdd(&g_acc[(b * 3 + tid) * 4 + 0], sum);
    }

    // ---- sparse positive cells ----
    const int cnt = min(g_pos_cnt, POSCAP);
    for (int k = bid * FTHREADS + tid; k < cnt; k += FGRID * FTHREADS) {
        int e = g_pos[k];
        int etask = e >> 16;
        int i = e & 0xFFFF;
        int elevel = etask % 3, eb = etask / 3;
        int eW, eHW, eoff; float es;
        level_params(elevel, eW, eHW, es, eoff);
        const float* epr = (elevel == 0) ? p0 : (elevel == 1) ? p1 : p2;
        const float* base = epr + (size_t)eb * 7 * eHW;
        int widxg = eb * CELLS_PER_BATCH + eoff + i;

        int wv = g_winner[widxg];
        float z = g_obj[widxg];
        g_winner[widxg] = 0;          // self-clean
        g_obj[widxg] = 0.0f;
        int gt = wv - 1;
        const float* gp = &g_gt[((size_t)etask * NGT + gt) * 6];

        float x = base[i];
        {
            float t = expf(-fabsf(x));
            float lg = log1pf(t);
            float prob = sigf(x);
            float ce = fmaxf(x, 0.0f) - x * z + lg;
            float pt = prob * z + (1.0f - prob) * (1.0f - z);
            float at = 0.25f * z + 0.75f * (1.0f - z);
            float om = 1.0f - pt;
            float fz = at * om * om * ce;
            float f0 = 0.75f * prob * prob * (fmaxf(x, 0.0f) + lg);
            atomicAdd(&g_acc[etask * 4 + 0], fz - f0);
        }
        float gx = (float)(i % eW), gy = (float)(i / eW);
        float tcx = gp[0] * es, tcy = gp[1] * es;
        float tw = gp[2], th = gp[3];

        float x1 = base[eHW + i],     x2 = base[2 * eHW + i];
        float x3 = base[3 * eHW + i], x4 = base[4 * eHW + i];
        float pcx = (sigf(x1) + gx) * es;
        float pcy = (sigf(x2) + gy) * es;
        float pw = expf(clamp5(x3)) * es;
        float ph = expf(clamp5(x4)) * es;

        float pX1 = pcx - pw * 0.5f, pY1 = pcy - ph * 0.5f;
        float pX2 = pcx + pw * 0.5f, pY2 = pcy + ph * 0.5f;
        float tX1 = tcx - tw * 0.5f, tY1 = tcy - th * 0.5f;
        float tX2 = tcx + tw * 0.5f, tY2 = tcy + th * 0.5f;

        float iw = fmaxf(fminf(pX2, tX2) - fmaxf(pX1, tX1), 0.0f);
        float ih = fmaxf(fminf(pY2, tY2) - fmaxf(pY1, tY1), 0.0f);
        float inter = iw * ih;
        float uni = pw * ph + tw * th - inter + EPSF;
        float iou = inter / uni;
        float rho2 = (pcx - tcx) * (pcx - tcx) + (pcy - tcy) * (pcy - tcy);
        float cw = fmaxf(pX2, tX2) - fminf(pX1, tX1);
        float ch = fmaxf(pY2, tY2) - fminf(pY1, tY1);
        float c2 = cw * cw + ch * ch + EPSF;
        const float PI = 3.14159265358979323846f;
        float dat = atanf(tw / (th + EPSF)) - atanf(pw / (ph + EPSF));
        float vv = (4.0f / (PI * PI)) * dat * dat;
        float alpha = vv / (1.0f - iou + vv + EPSF);
        float ciou = iou - rho2 / c2 - alpha * vv;
        atomicAdd(&g_acc[etask * 4 + 1], 1.0f - ciou);

        float p5 = base[5 * eHW + i], p6 = base[6 * eHW + i];
        float f0 = sigf(p5), f1 = sigf(p6);
        float d0 = fabsf(f0 - gp[4]), d1 = fabsf(f1 - gp[5]);
        float sl = (d0 < 1.0f ? 0.5f * d0 * d0 : d0 - 0.5f)
                 + (d1 < 1.0f ? 0.5f * d1 * d1 : d1 - 0.5f);
        atomicAdd(&g_acc[etask * 4 + 2], sl);
        atomicAdd(&g_acc[etask * 4 + 3], 1.0f);
    }

    // ---- last CTA: final reduction + state reset ----
    __threadfence();
    __shared__ int slast;
    if (tid == 0) slast = (atomicAdd(&g_done, 1u) == FGRID - 1) ? 1 : 0;
    __syncthreads();
    if (!slast) return;

    float vfin = 0.0f;
    if (tid < NTASK) {
        int lvv = tid % 3;
        float HWf = (lvv == 0) ? 25600.0f : (lvv == 1) ? 6400.0f : 1600.0f;
        float f  = g_acc[tid * 4 + 0];
        float bx = g_acc[tid * 4 + 1];
        float ft = g_acc[tid * 4 + 2];
        float pm = g_acc[tid * 4 + 3];
        float npos = fmaxf(pm, 1.0f);
        vfin = (f / HWf) + 5.0f * (bx / npos) + (ft / npos);
    }
    sfin[tid] = vfin;
    __syncthreads();
    for (int j = tid; j < NTASK * 4; j += FTHREADS) g_acc[j] = 0.0f;
    if (tid == 0) { g_pos_cnt = 0; g_done = 0u; }
    for (int st = FTHREADS / 2; st > 0; st >>= 1) {
        if (tid < st) sfin[tid] += sfin[tid + st];
        __syncthreads();
    }
    if (tid == 0) out[0] = sfin[0] / (float)NB;
}

// ---------------------------------------------------------------------------
extern "C" void kernel_launch(void* const* d_in, const int* in_sizes, int n_in,
                              void* d_out, int out_size)
{
    const float* p0  = (const float*)d_in[0];
    const float* p1  = (const float*)d_in[1];
    const float* p2  = (const float*)d_in[2];
    const float* tgt = (const float*)d_in[3];
    float* out = (float*)d_out;

    assign_kernel<<<NTASK * NGT, 128>>>(p0, p1, p2, tgt);
    fused_kernel<<<FGRID, FTHREADS>>>(p0, p1, p2, out);
}

// round 16
// speedup vs baseline: 1.6050x; 1.0743x over previous
#include <cuda_runtime.h>
#include <math.h>
#include <float.h>

// ---------------------------------------------------------------------------
// PFDetLoss — R16: dense focal CTAs merged INTO the assign launch (dense work
// overlaps the mostly-idle assign wave); small sparse+final second kernel.
// 2 launches, self-cleaning state.
// ---------------------------------------------------------------------------

#define IMGF 1280.0f
#define EPSF 1e-7f
#define RADIUSF 2.5f
#define NCAND 10
#define CAP 1024

#define CELLS_PER_BATCH 33600      // 25600 + 6400 + 1600
#define NB 64
#define NGT 40
#define NTASK (NB * 3)
#define ASSIGN_GRID (NTASK * NGT)  // 7680
#define DGRID 512                  // dense: 64 batches x 8 eighths
#define QF4 1050                   // float4 per eighth (8400 per batch)
#define POSCAP (NTASK * NGT * NCAND)
#define SGRID 64                   // sparse+final grid
#define LUTN 4096
#define LUT_S (4096.0f / 24.0f)
#define LUT_STEP (24.0f / 4096.0f)

// state: zero-initialized at load; self-cleaning every call.
__device__ int          g_winner[NB * CELLS_PER_BATCH];  // 0 = none, gt+1
__device__ float        g_obj   [NB * CELLS_PER_BATCH];
__device__ float        g_gt    [NTASK * NGT * 6];       // cxg, cyg, tw, th, fx, fy
__device__ float        g_acc   [NTASK * 4];             // focal, box, foot, pm
__device__ int          g_pos   [POSCAP];                // (task<<16)|cell
__device__ int          g_pos_cnt;
__device__ unsigned int g_done;
__device__ unsigned int g_lut_ready;                     // builder CTAs completed
__device__ float4       g_lut   [LUTN / 4];

__device__ __forceinline__ float sigf(float x) { return 1.0f / (1.0f + expf(-x)); }
__device__ __forceinline__ float clamp5(float x) { return fminf(fmaxf(x, -5.0f), 5.0f); }

__device__ __forceinline__ void level_params(int level, int& W, int& HW, float& s, int& off) {
    if (level == 0)      { W = 160; HW = 25600; s = 8.0f  / IMGF; off = 0; }
    else if (level == 1) { W = 80;  HW = 6400;  s = 16.0f / IMGF; off = 25600; }
    else                 { W = 40;  HW = 1600;  s = 32.0f / IMGF; off = 32000; }
}

__device__ __forceinline__ float focal0_exact(float x) {
    float t = expf(-fabsf(x));
    float r = 1.0f / (1.0f + t);
    float prob = (x >= 0.0f) ? r : t * r;
    float ce0 = fmaxf(x, 0.0f) + log1pf(t);
    return 0.75f * prob * prob * ce0;
}

__device__ __forceinline__ int nearest_cell(float c, int n) {
    int lo = (int)floorf(c);
    int g0 = min(max(lo, 0), n - 1);
    int g1 = min(max(lo + 1, 0), n - 1);
    float f0 = ((float)g0 - c) * ((float)g0 - c);
    float f1 = ((float)g1 - c) * ((float)g1 - c);
    return (f1 < f0) ? g1 : g0;
}

__device__ __forceinline__ void cell_iou_cost(
    const float* __restrict__ base, int HW, int i, float gx, float gy, float s,
    float gX1, float gY1, float gX2, float gY2, float gArea,
    float& iou, float& cost)
{
    float o  = base[i];
    float x1 = base[HW + i],     x2 = base[2 * HW + i];
    float x3 = base[3 * HW + i], x4 = base[4 * HW + i];
    float pcx = (sigf(x1) + gx) * s;
    float pcy = (sigf(x2) + gy) * s;
    float pw = expf(clamp5(x3)) * s;
    float ph = expf(clamp5(x4)) * s;
    float pX1 = pcx - pw * 0.5f, pY1 = pcy - ph * 0.5f;
    float pX2 = pcx + pw * 0.5f, pY2 = pcy + ph * 0.5f;

    float ltx = fmaxf(pX1, gX1), lty = fmaxf(pY1, gY1);
    float rbx = fminf(pX2, gX2), rby = fminf(pY2, gY2);
    float iw = fmaxf(rbx - ltx, 0.0f), ih = fmaxf(rby - lty, 0.0f);
    float inter = iw * ih;
    float pArea = (pX2 - pX1) * (pY2 - pY1);
    iou = inter / (pArea + gArea - inter + EPSF);

    float clsc = fmaxf(-o, 0.0f) + log1pf(expf(-fabsf(o)));
    cost = clsc - 3.0f * logf(iou + EPSF);
}

__device__ __forceinline__ void claim_cell(int task, int cbase, int c, int gt, float bestiou) {
    int old = atomicMax(&g_winner[cbase + c], gt + 1);
    if (old == 0) {
        int slot = atomicAdd(&g_pos_cnt, 1);
        g_pos[slot] = (task << 16) | c;
    }
    atomicMax((int*)&g_obj[cbase + c], __float_as_int(bestiou));
}

// 4-element LUT sum for one float4 of logits (saturating u32 cvt = 1 clamp)
__device__ __forceinline__ float lut4sum(const float* __restrict__ slut, float4 v) {
    unsigned i0 = __float2uint_rn(fmaf(v.x, LUT_S, 2048.0f));
    unsigned i1 = __float2uint_rn(fmaf(v.y, LUT_S, 2048.0f));
    unsigned i2 = __float2uint_rn(fmaf(v.z, LUT_S, 2048.0f));
    unsigned i3 = __float2uint_rn(fmaf(v.w, LUT_S, 2048.0f));
    i0 = min(i0, (unsigned)(LUTN - 1));
    i1 = min(i1, (unsigned)(LUTN - 1));
    i2 = min(i2, (unsigned)(LUTN - 1));
    i3 = min(i3, (unsigned)(LUTN - 1));
    return (slut[i0] + slut[i1]) + (slut[i2] + slut[i3]);
}

// ---------------------------------------------------------------------------
// Kernel 1: bids [0, 7680) = assign (one CTA per task,gt); bids >= 7680 =
// dense focal CTAs. Shared-memory union keeps occupancy at ~13 CTAs/SM.
__global__ __launch_bounds__(128) void assign_dense_kernel(
    const float* __restrict__ p0, const float* __restrict__ p1,
    const float* __restrict__ p2, const float* __restrict__ tgt)
{
    __shared__ __align__(16) char s_union[16384];
    __shared__ int   s_cnt;
    __shared__ int   s_sel[NCAND];
    __shared__ float s_bestiou;
    __shared__ int   s_npos;
    __shared__ float sredD[3][4];

    const int bid = blockIdx.x;
    const int tid = threadIdx.x;
    const int wid = tid >> 5;
    const int lane = tid & 31;

    // ======================= dense CTAs =======================
    if (bid >= ASSIGN_GRID) {
        const int d = bid - ASSIGN_GRID;
        const int b = d >> 3;
        const int q = d & 7;

        // wait for LUT builders (bids<32 retire thousands of CTAs before us;
        // the spin is belt-and-suspenders and should never iterate)
        if (tid == 0) {
            while (*((volatile unsigned*)&g_lut_ready) < 32u) __nanosleep(64);
        }
        __syncthreads();
        __threadfence();

        float* slut = (float*)s_union;      // 16KB view
        float4* slut4 = (float4*)s_union;
#pragma unroll
        for (int k = 0; k < 8; k++) slut4[tid + k * 128] = g_lut[tid + k * 128];
        __syncthreads();

        const float4* c00 = (const float4*)(p0 + (size_t)b * 7 * 25600);
        const float4* c01 = (const float4*)(p1 + (size_t)b * 7 * 6400);
        const float4* c02 = (const float4*)(p2 + (size_t)b * 7 * 1600);

        const int jlo = q * QF4, jhi = jlo + QF4;
        float a0 = 0.0f, a1 = 0.0f, a2 = 0.0f;
        {   // level 0 segment: [0, 6400)
            int hi = min(jhi, 6400);
            for (int j = jlo + tid; j < hi; j += 128) a0 += lut4sum(slut, c00[j]);
        }
        {   // level 1 segment: [6400, 8000)
            int lo = max(jlo, 6400), hi = min(jhi, 8000);
            for (int j = lo + tid; j < hi; j += 128) a1 += lut4sum(slut, c01[j - 6400]);
        }
        {   // level 2 segment: [8000, 8400)
            int lo = max(jlo, 8000);
            for (int j = lo + tid; j < jhi; j += 128) a2 += lut4sum(slut, c02[j - 8000]);
        }
#pragma unroll
        for (int o = 16; o > 0; o >>= 1) {
            a0 += __shfl_down_sync(0xffffffffu, a0, o);
            a1 += __shfl_down_sync(0xffffffffu, a1, o);
            a2 += __shfl_down_sync(0xffffffffu, a2, o);
        }
        if (lane == 0) { sredD[0][wid] = a0; sredD[1][wid] = a1; sredD[2][wid] = a2; }
        __syncthreads();
        if (tid < 3) {
            float sum = (sredD[tid][0] + sredD[tid][1]) + (sredD[tid][2] + sredD[tid][3]);
            if (sum != 0.0f) atomicAdd(&g_acc[(b * 3 + tid) * 4 + 0], sum);
        }
        return;
    }

    // ======================= assign CTAs =======================
    // smem union views (disjoint from dense path by bid)
    float* s_cost = (float*)s_union;                 // 4KB
    int*   s_idx  = (int*)(s_union + 4096);          // 4KB
    float* s_iou  = (float*)(s_union + 8192);        // 4KB
    float* rf     = (float*)(s_union + 12288);       // 512B

    if (bid < 32) {   // LUT build: 32 CTAs x 128 threads = 4096 entries
        int e = bid * 128 + tid;
        float x = ((float)(e - 2048)) * LUT_STEP;
        ((float*)g_lut)[e] = focal0_exact(x);
        __threadfence();
        __syncthreads();
        if (tid == 0) atomicAdd(&g_lut_ready, 1u);
    }

    const int gt   = bid % NGT;
    const int task = bid / NGT;
    const int level = task % 3;
    const int b     = task / 3;

    const float* t = tgt + ((size_t)b * NGT + gt) * 7;
    const float cls = t[0];
    const float cx = t[1], cy = t[2], w = t[3], h = t[4];
    const float fx = t[5], fy = t[6];

    const float size = fmaxf(w, h) * IMGF;
    bool sm;
    if (level == 0)      sm = (size < 128.0f);
    else if (level == 1) sm = (size >= 48.0f) && (size < 288.0f);
    else                 sm = (size >= 128.0f);
    if (!(cls == 0.0f && sm)) return;   // invalid GT: exact no-op

    int W, HW, off; float s;
    level_params(level, W, HW, s, off);
    const float* pr = (level == 0) ? p0 : (level == 1) ? p1 : p2;
    const float* base = pr + (size_t)b * 7 * HW;
    const int cbase = b * CELLS_PER_BATCH + off;

    const float cxg = cx / s, cyg = cy / s;
    const float bx1 = (cx - w * 0.5f) / s, bx2 = (cx + w * 0.5f) / s;
    const float by1 = (cy - h * 0.5f) / s, by2 = (cy + h * 0.5f) / s;

    const float gX1 = cx - w * 0.5f, gY1 = cy - h * 0.5f;
    const float gX2 = cx + w * 0.5f, gY2 = cy + h * 0.5f;
    const float gArea = (gX2 - gX1) * (gY2 - gY1);

    int gx_lo = max(0,     (int)floorf(fminf(cxg - RADIUSF, bx1)) - 1);
    int gx_hi = min(W - 1, (int)ceilf (fmaxf(cxg + RADIUSF, bx2)) + 1);
    int gy_lo = max(0,     (int)floorf(fminf(cyg - RADIUSF, by1)) - 1);
    int gy_hi = min(W - 1, (int)ceilf (fmaxf(cyg + RADIUSF, by2)) + 1);
    int rw = gx_hi - gx_lo + 1;
    int rh = gy_hi - gy_lo + 1;
    int ncells = (rw > 0 && rh > 0) ? rw * rh : 0;

    if (tid == 0) s_cnt = 0;
    __syncthreads();

    float iousum_l = 0.0f;
    for (int k = tid; k < ncells; k += 128) {
        int gxi = gx_lo + k % rw;
        int gyi = gy_lo + k / rw;
        float gx = (float)gxi, gy = (float)gyi;
        bool inc = (fabsf(gx - cxg) < RADIUSF) && (fabsf(gy - cyg) < RADIUSF);
        bool inb = (gx >= bx1) && (gx < bx2) && (gy >= by1) && (gy < by2);
        if (!(inc || inb)) continue;
        int i = gyi * W + gxi;
        float iou, cost;
        cell_iou_cost(base, HW, i, gx, gy, s, gX1, gY1, gX2, gY2, gArea, iou, cost);
        iousum_l += iou;
        int slot = atomicAdd(&s_cnt, 1);
        if (slot < CAP) { s_cost[slot] = cost; s_idx[slot] = i; s_iou[slot] = iou; }
    }

    // deterministic iou_sum reduction (fixed tree)
    rf[tid] = iousum_l;
    __syncthreads();
    for (int st = 64; st > 0; st >>= 1) {
        if (tid < st) rf[tid] += rf[tid + st];
        __syncthreads();
    }
    const float iou_sum = rf[0];
    const int n_cand = min(s_cnt, CAP);
    __syncthreads();

    if (n_cand == 0) {
        if (tid == 0) {
            int gxi = nearest_cell(cxg, W);
            int gyi = nearest_cell(cyg, W);
            int i = gyi * W + gxi;
            float iou, cost;
            cell_iou_cost(base, HW, i, (float)gxi, (float)gyi, s,
                          gX1, gY1, gX2, gY2, gArea, iou, cost);
            claim_cell(task, cbase, i, gt, iou);
            float* gp = &g_gt[((size_t)task * NGT + gt) * 6];
            gp[0] = cxg; gp[1] = cyg;
            gp[2] = expf(logf(w / s + EPSF)) * s;
            gp[3] = expf(logf(h / s + EPSF)) * s;
            gp[4] = fx; gp[5] = fy;
        }
        return;
    }

    // ---- warp 0 does all selection rounds (no block barriers inside) ----
    if (wid == 0) {
        int np = (int)floorf(iou_sum);
        int hi = (NCAND < n_cand) ? NCAND : n_cand;
        if (np < 1) np = 1;
        if (np > hi) np = hi;
        if (lane == 0) s_npos = np;

        for (int r = 0; r < np; r++) {
            float mv = FLT_MAX; int mi = 0x7fffffff; int ms = -1;
            for (int k = lane; k < n_cand; k += 32) {
                float v = s_cost[k]; int ii = s_idx[k];
                if (v < mv || (v == mv && ii < mi)) { mv = v; mi = ii; ms = k; }
            }
#pragma unroll
            for (int o = 16; o > 0; o >>= 1) {
                float ov = __shfl_down_sync(0xffffffffu, mv, o);
                int   oi = __shfl_down_sync(0xffffffffu, mi, o);
                int   os = __shfl_down_sync(0xffffffffu, ms, o);
                if (ov < mv || (ov == mv && oi < mi)) { mv = ov; mi = oi; ms = os; }
            }
            if (lane == 0) {
                s_sel[r] = mi;
                if (r == 0) s_bestiou = s_iou[ms];
                s_cost[ms] = FLT_MAX;
            }
            __syncwarp();
        }
    }
    __syncthreads();

    const int n_pos = s_npos;
    if (tid < n_pos) {
        claim_cell(task, cbase, s_sel[tid], gt, s_bestiou);
    }
    if (tid == 0) {
        float* gp = &g_gt[((size_t)task * NGT + gt) * 6];
        gp[0] = cxg; gp[1] = cyg;
        gp[2] = expf(logf(w / s + EPSF)) * s;
        gp[3] = expf(logf(h / s + EPSF)) * s;
        gp[4] = fx; gp[5] = fy;
    }
}

// ---------------------------------------------------------------------------
// Kernel 2: sparse positive terms + final reduction + state cleanup.
__global__ __launch_bounds__(128) void sparse_final_kernel(
    const float* __restrict__ p0, const float* __restrict__ p1,
    const float* __restrict__ p2, float* __restrict__ out)
{
    __shared__ float sfin[128];
    const int tid = threadIdx.x;
    const int bid = blockIdx.x;

    const int cnt = min(g_pos_cnt, POSCAP);
    for (int k = bid * 128 + tid; k < cnt; k += SGRID * 128) {
        int e = g_pos[k];
        int etask = e >> 16;
        int i = e & 0xFFFF;
        int elevel = etask % 3, eb = etask / 3;
        int eW, eHW, eoff; float es;
        level_params(elevel, eW, eHW, es, eoff);
        const float* epr = (elevel == 0) ? p0 : (elevel == 1) ? p1 : p2;
        const float* base = epr + (size_t)eb * 7 * eHW;
        int widxg = eb * CELLS_PER_BATCH + eoff + i;

        int wv = g_winner[widxg];
        float z = g_obj[widxg];
        g_winner[widxg] = 0;          // self-clean
        g_obj[widxg] = 0.0f;
        int gt = wv - 1;
        const float* gp = &g_gt[((size_t)etask * NGT + gt) * 6];

        float x = base[i];
        {   // focal correction: f(x,z) - f(x,0), exact fp32
            float t = expf(-fabsf(x));
            float lg = log1pf(t);
            float prob = sigf(x);
            float ce = fmaxf(x, 0.0f) - x * z + lg;
            float pt = prob * z + (1.0f - prob) * (1.0f - z);
            float at = 0.25f * z + 0.75f * (1.0f - z);
            float om = 1.0f - pt;
            float fz = at * om * om * ce;
            float f0 = 0.75f * prob * prob * (fmaxf(x, 0.0f) + lg);
            atomicAdd(&g_acc[etask * 4 + 0], fz - f0);
        }
        float gx = (float)(i % eW), gy = (float)(i / eW);
        float tcx = gp[0] * es, tcy = gp[1] * es;
        float tw = gp[2], th = gp[3];

        float x1 = base[eHW + i],     x2 = base[2 * eHW + i];
        float x3 = base[3 * eHW + i], x4 = base[4 * eHW + i];
        float pcx = (sigf(x1) + gx) * es;
        float pcy = (sigf(x2) + gy) * es;
        float pw = expf(clamp5(x3)) * es;
        float ph = expf(clamp5(x4)) * es;

        float pX1 = pcx - pw * 0.5f, pY1 = pcy - ph * 0.5f;
        float pX2 = pcx + pw * 0.5f, pY2 = pcy + ph * 0.5f;
        float tX1 = tcx - tw * 0.5f, tY1 = tcy - th * 0.5f;
        float tX2 = tcx + tw * 0.5f, tY2 = tcy + th * 0.5f;

        float iw = fmaxf(fminf(pX2, tX2) - fmaxf(pX1, tX1), 0.0f);
        float ih = fmaxf(fminf(pY2, tY2) - fmaxf(pY1, tY1), 0.0f);
        float inter = iw * ih;
        float uni = pw * ph + tw * th - inter + EPSF;
        float iou = inter / uni;
        float rho2 = (pcx - tcx) * (pcx - tcx) + (pcy - tcy) * (pcy - tcy);
        float cw = fmaxf(pX2, tX2) - fminf(pX1, tX1);
        float ch = fmaxf(pY2, tY2) - fminf(pY1, tY1);
        float c2 = cw * cw + ch * ch + EPSF;
        const float PI = 3.14159265358979323846f;
        float dat = atanf(tw / (th + EPSF)) - atanf(pw / (ph + EPSF));
        float vv = (4.0f / (PI * PI)) * dat * dat;
        float alpha = vv / (1.0f - iou + vv + EPSF);
        float ciou = iou - rho2 / c2 - alpha * vv;
        atomicAdd(&g_acc[etask * 4 + 1], 1.0f - ciou);

        float p5 = base[5 * eHW + i], p6 = base[6 * eHW + i];
        float f0 = sigf(p5), f1 = sigf(p6);
        float d0 = fabsf(f0 - gp[4]), d1 = fabsf(f1 - gp[5]);
        float sl = (d0 < 1.0f ? 0.5f * d0 * d0 : d0 - 0.5f)
                 + (d1 < 1.0f ? 0.5f * d1 * d1 : d1 - 0.5f);
        atomicAdd(&g_acc[etask * 4 + 2], sl);
        atomicAdd(&g_acc[etask * 4 + 3], 1.0f);
    }

    // ---- last CTA: final reduction + state reset ----
    __threadfence();
    __shared__ int slast;
    if (tid == 0) slast = (atomicAdd(&g_done, 1u) == SGRID - 1) ? 1 : 0;
    __syncthreads();
    if (!slast) return;

    float vfin = 0.0f;
    for (int t = tid; t < NTASK; t += 128) {
        int lvv = t % 3;
        float HWf = (lvv == 0) ? 25600.0f : (lvv == 1) ? 6400.0f : 1600.0f;
        float f  = g_acc[t * 4 + 0];
        float bx = g_acc[t * 4 + 1];
        float ft = g_acc[t * 4 + 2];
        float pm = g_acc[t * 4 + 3];
        float npos = fmaxf(pm, 1.0f);
        vfin += (f / HWf) + 5.0f * (bx / npos) + (ft / npos);
    }
    sfin[tid] = vfin;
    __syncthreads();
    // reset state for next call (g_acc reads done)
    for (int j = tid; j < NTASK * 4; j += 128) g_acc[j] = 0.0f;
    if (tid == 0) { g_pos_cnt = 0; g_done = 0u; g_lut_ready = 0u; }
    for (int st = 64; st > 0; st >>= 1) {
        if (tid < st) sfin[tid] += sfin[tid + st];
        __syncthreads();
    }
    if (tid == 0) out[0] = sfin[0] / (float)NB;
}

// ---------------------------------------------------------------------------
extern "C" void kernel_launch(void* const* d_in, const int* in_sizes, int n_in,
                              void* d_out, int out_size)
{
    const float* p0  = (const float*)d_in[0];
    const float* p1  = (const float*)d_in[1];
    const float* p2  = (const float*)d_in[2];
    const float* tgt = (const float*)d_in[3];
    float* out = (float*)d_out;

    assign_dense_kernel<<<ASSIGN_GRID + DGRID, 128>>>(p0, p1, p2, tgt);
    sparse_final_kernel<<<SGRID, 128>>>(p0, p1, p2, out);
}